// round 17
// baseline (speedup 1.0000x reference)
#include <cuda_runtime.h>
#include <cuda_bf16.h>
#include <cstdint>

// Problem constants
#define B_ 128
#define T_ 2048
#define D_ 128
#define H_ 512
#define G_ 2048   // 4*H
#define K_ 640    // H + D
#define L_ 10

// Tiling: 4 batch groups x 64 column-tile CTAs (n=32 each) -> occupancy 2.
// Within a CTA: 8 warps = 4 k-chunks (160) x 2 n-halves (16).
#define MT 4
#define NT 64
#define NBLK (MT*NT)
#define THREADS 256

// Smem strides (bf16 elements / floats)
#define WS_STR 648
#define AS_STR 648
#define GS_STR 36

// Smem byte offsets
#define OFF_WS 0                        // weights 32x648x2 = 41472
#define OFF_AS 41472                    // A tile  32x648x2 = 41472
#define OFF_GS 82944                    // 4 slabs of [32][36] fp32 = 18432
#define OFF_CS 101376                   // fp32 cell [32][8] = 1024
#define OFF_BS 102400                   // fp32 bias [32] = 128
#define SMEM_BYTES 102528               // x2 CTAs = 205056 <= 227KB

// Device-global scratch (all explicitly aligned — R2 lesson)
__device__ __align__(256) __nv_bfloat16 g_Wpk[G_][K_];
__device__ __align__(256) float         g_bpk[G_];
__device__ __align__(256) __nv_bfloat16 g_h[2][B_][H_];
__device__ __align__(256) __nv_bfloat16 g_xB[(size_t)B_*T_*D_];
__device__ __align__(256) unsigned      g_flag[MT*NT*32];   // per-CTA flags, 128B apart

__device__ __forceinline__ float tanhapx(float x){
    float y; asm("tanh.approx.f32 %0, %1;" : "=f"(y) : "f"(x)); return y;
}
__device__ __forceinline__ float sigm(float x){
    return fmaf(tanhapx(0.5f*x), 0.5f, 0.5f);
}

#define CPA16(dst, src) asm volatile("cp.async.cg.shared.global [%0], [%1], 16;" :: "r"(dst), "l"(src))

// ---------------- setup kernels ----------------
__global__ void xconv_kernel(const float* __restrict__ x){
    size_t i = (size_t)blockIdx.x*blockDim.x + threadIdx.x;
    float4 v = ((const float4*)x)[i];
    __nv_bfloat162* dst = (__nv_bfloat162*)g_xB;
    dst[2*i]   = __floats2bfloat162_rn(v.x, v.y);
    dst[2*i+1] = __floats2bfloat162_rn(v.z, v.w);
}

__global__ void pack_kernel(const float* __restrict__ W_ih,
                            const float* __restrict__ W_hh,
                            const float* __restrict__ b){
    int p = blockIdx.x;
    int j = p >> 2;
    int g = p & 3;
    int src = g*H_ + j;
    for (int k = threadIdx.x; k < K_; k += blockDim.x){
        float v = (k < H_) ? W_hh[src*H_ + k] : W_ih[src*D_ + (k - H_)];
        g_Wpk[p][k] = __float2bfloat16_rn(v);
    }
    if (threadIdx.x == 0) g_bpk[p] = b[src];
}

__global__ void init_kernel(){
    int i = blockIdx.x*blockDim.x + threadIdx.x;
    if (i < B_*H_) ((__nv_bfloat16*)g_h)[i] = __float2bfloat16(0.0f);
    if (i < MT*NT*32) g_flag[i] = 0u;
}

// ---------------- main persistent scan kernel ----------------
__global__ void __launch_bounds__(THREADS, 2) lstm_scan(){
    extern __shared__ char smc[];
    const uint32_t sb = (uint32_t)__cvta_generic_to_shared(smc);
    float* Gs = (float*)(smc + OFF_GS);
    float* cs = (float*)(smc + OFF_CS);
    float* bs = (float*)(smc + OFF_BS);

    const int tid = threadIdx.x;
    const int nb_ = blockIdx.x & 63;
    const int mb_ = blockIdx.x >> 6;
    const int m0 = mb_ * 32;
    const int p0 = nb_ * 32;
    const int j0 = nb_ * 8;

    // Load weight slice once: 32 rows x 640 bf16 (80 float4 per row)
    {
        const float4* src = (const float4*)&g_Wpk[p0][0];
        for (int i = tid; i < 32*80; i += THREADS){
            int r = i/80, c = i%80;
            *(float4*)(smc + OFF_WS + r*WS_STR*2 + c*16) = __ldcg(src + (size_t)r*80 + c);
        }
    }
    if (tid < 32) bs[tid] = g_bpk[p0 + tid];
    if (tid < 32*8) cs[tid] = 0.0f;
    __syncthreads();

    const int lane = tid & 31, warp = tid >> 5;
    const int grp = lane >> 2, tig = lane & 3;
    const int wk  = warp & 3;        // k-chunk (160 wide = 10 q-steps)
    const int wn2 = (warp >> 2) & 1; // n-half (16 cols)

    // ---- B fragments: load ONCE into registers for all T steps ----
    uint32_t bf[10][4];
    {
        const int brow = ((lane >> 4) << 3) + (lane & 7);
        const int bcol8 = ((lane >> 3) & 1) * 8;
        #pragma unroll
        for (int q = 0; q < 10; ++q){
            uint32_t addr = sb + OFF_WS +
                (uint32_t)(((wn2*16 + brow)*WS_STR + wk*160 + q*16 + bcol8)*2);
            asm volatile("ldmatrix.sync.aligned.m8n8.x4.shared.b16 {%0,%1,%2,%3}, [%4];"
                : "=r"(bf[q][0]),"=r"(bf[q][1]),"=r"(bf[q][2]),"=r"(bf[q][3])
                : "r"(addr));
        }
    }

    // A-fragment ldmatrix base addresses
    uint32_t aBase[2];
    #pragma unroll
    for (int mh = 0; mh < 2; ++mh)
        aBase[mh] = sb + OFF_AS +
            (uint32_t)(((mh*16 + (lane & 15))*AS_STR + (lane >> 4)*8)*2);

    // This CTA's flag + the two flags warp0's lane polls (64 producers)
    unsigned* myFlag = &g_flag[(mb_*NT + nb_)*32];
    const unsigned* poFlag0 = &g_flag[(mb_*NT + lane)*32];
    const unsigned* poFlag1 = &g_flag[(mb_*NT + 32 + lane)*32];

    for (int t = 0; t < T_; ++t){
        // ---- bulk load A tile via cp.async: h (32x512) + x (32x128) ----
        {
            const __nv_bfloat16* hsrc = &g_h[t & 1][m0][0];
            #pragma unroll
            for (int i = 0; i < 8; ++i){
                int s = tid + i*THREADS;
                int r = s >> 6, c = s & 63;
                CPA16(sb + OFF_AS + (uint32_t)(r*AS_STR*2 + c*16), hsrc + r*H_ + c*8);
            }
            const __nv_bfloat16* xsrc = g_xB + ((size_t)m0*T_ + t)*D_;
            #pragma unroll
            for (int i = 0; i < 2; ++i){
                int s = tid + i*THREADS;
                int r = s >> 4, c = s & 15;
                CPA16(sb + OFF_AS + (uint32_t)(r*AS_STR*2 + 1024 + c*16),
                      xsrc + (size_t)r*T_*D_ + c*8);
            }
            asm volatile("cp.async.commit_group;");
            asm volatile("cp.async.wait_group 0;");
        }
        __syncthreads();

        // ---- MMA: m32 x n16 x k160 per warp; A frags double-buffered ----
        float acc[2][2][4] = {};
        {
            const uint32_t kbase = (uint32_t)(wk*320);
            uint32_t a[2][2][4];
            #pragma unroll
            for (int mh = 0; mh < 2; ++mh)
                asm volatile("ldmatrix.sync.aligned.m8n8.x4.shared.b16 {%0,%1,%2,%3}, [%4];"
                    : "=r"(a[0][mh][0]),"=r"(a[0][mh][1]),"=r"(a[0][mh][2]),"=r"(a[0][mh][3])
                    : "r"(aBase[mh] + kbase));
            #pragma unroll
            for (int q = 0; q < 10; ++q){
                const int cur = q & 1, nxt = cur ^ 1;
                if (q < 9){
                    #pragma unroll
                    for (int mh = 0; mh < 2; ++mh)
                        asm volatile("ldmatrix.sync.aligned.m8n8.x4.shared.b16 {%0,%1,%2,%3}, [%4];"
                            : "=r"(a[nxt][mh][0]),"=r"(a[nxt][mh][1]),
                              "=r"(a[nxt][mh][2]),"=r"(a[nxt][mh][3])
                            : "r"(aBase[mh] + kbase + (q+1)*32));
                }
                #pragma unroll
                for (int mh = 0; mh < 2; ++mh){
                    float* A0 = acc[mh][0];
                    float* A1 = acc[mh][1];
                    asm("mma.sync.aligned.m16n8k16.row.col.f32.bf16.bf16.f32 "
                        "{%0,%1,%2,%3}, {%4,%5,%6,%7}, {%8,%9}, {%0,%1,%2,%3};"
                        : "+f"(A0[0]),"+f"(A0[1]),"+f"(A0[2]),"+f"(A0[3])
                        : "r"(a[cur][mh][0]),"r"(a[cur][mh][1]),
                          "r"(a[cur][mh][2]),"r"(a[cur][mh][3]),
                          "r"(bf[q][0]),"r"(bf[q][1]));
                    asm("mma.sync.aligned.m16n8k16.row.col.f32.bf16.bf16.f32 "
                        "{%0,%1,%2,%3}, {%4,%5,%6,%7}, {%8,%9}, {%0,%1,%2,%3};"
                        : "+f"(A1[0]),"+f"(A1[1]),"+f"(A1[2]),"+f"(A1[3])
                        : "r"(a[cur][mh][0]),"r"(a[cur][mh][1]),
                          "r"(a[cur][mh][2]),"r"(a[cur][mh][3]),
                          "r"(bf[q][2]),"r"(bf[q][3]));
                }
            }
        }

        // ---- scatter partial gates to slab[wk] ----
        {
            float* Gw = Gs + wk*(32*GS_STR);
            #pragma unroll
            for (int mh = 0; mh < 2; ++mh){
                int r0 = (mh*16 + grp)*GS_STR, r1 = r0 + 8*GS_STR;
                #pragma unroll
                for (int hi = 0; hi < 2; ++hi){
                    int c = wn2*16 + hi*8 + 2*tig;
                    float* A = acc[mh][hi];
                    *(float2*)&Gw[r0 + c] = make_float2(A[0], A[1]);
                    *(float2*)&Gw[r1 + c] = make_float2(A[2], A[3]);
                }
            }
        }
        __syncthreads();

        // ---- reduce 4 k-partials + LSTM cell update (1 (b,j) per thread) ----
        const int wbuf = (t + 1) & 1;
        {
            int b = tid >> 3;
            int j = tid & 7;
            float4 s = *(const float4*)&bs[4*j];
            #pragma unroll
            for (int w = 0; w < 4; ++w){
                float4 v = *(const float4*)&Gs[w*(32*GS_STR) + b*GS_STR + 4*j];
                s.x += v.x; s.y += v.y; s.z += v.z; s.w += v.w;
            }
            float c_old = cs[b*8 + j];
            float cn = sigm(s.y)*c_old + sigm(s.x)*tanhapx(s.z);
            float hn = sigm(s.w)*tanhapx(cn);
            cs[b*8 + j] = cn;
            unsigned short hu = __bfloat16_as_ushort(__float2bfloat16_rn(hn));
            __nv_bfloat16* dst = &g_h[wbuf][m0 + b][j0 + j];
            asm volatile("st.global.cg.u16 [%0], %1;" :: "l"(dst), "h"(hu));
        }
        __syncthreads();

        // ---- flag barrier: one release-store, 64 parallel acquire-polls ----
        if (tid == 0){
            asm volatile("st.global.release.gpu.u32 [%0], %1;"
                         :: "l"(myFlag), "r"((unsigned)(t + 1)));
        }
        if (warp == 0){
            unsigned v0, v1;
            do {
                asm volatile("ld.global.acquire.gpu.u32 %0, [%1];" : "=r"(v0) : "l"(poFlag0));
            } while (v0 < (unsigned)(t + 1));
            do {
                asm volatile("ld.global.acquire.gpu.u32 %0, [%1];" : "=r"(v1) : "l"(poFlag1));
            } while (v1 < (unsigned)(t + 1));
        }
        __syncthreads();
    }
}

// ---------------- output head: logits + softmax ----------------
__global__ void out_kernel(const float* __restrict__ W_out, float* __restrict__ out){
    int b = blockIdx.x;
    int lane = threadIdx.x;
    float acc[L_];
    #pragma unroll
    for (int l = 0; l < L_; ++l) acc[l] = 0.0f;
    for (int k = lane; k < H_; k += 32){
        float hv = __bfloat162float(g_h[0][b][k]);   // T even -> final h in buffer 0
        #pragma unroll
        for (int l = 0; l < L_; ++l) acc[l] += hv * __ldg(&W_out[l*H_ + k]);
    }
    #pragma unroll
    for (int l = 0; l < L_; ++l){
        #pragma unroll
        for (int o = 16; o; o >>= 1) acc[l] += __shfl_xor_sync(0xffffffffu, acc[l], o);
    }
    if (lane == 0){
        float mx = acc[0];
        #pragma unroll
        for (int l = 1; l < L_; ++l) mx = fmaxf(mx, acc[l]);
        float s = 0.0f;
        #pragma unroll
        for (int l = 0; l < L_; ++l){ acc[l] = expf(acc[l] - mx); s += acc[l]; }
        float inv = 1.0f / s;
        #pragma unroll
        for (int l = 0; l < L_; ++l) out[b*L_ + l] = acc[l] * inv;
    }
}

// ---------------- launch ----------------
extern "C" void kernel_launch(void* const* d_in, const int* in_sizes, int n_in,
                              void* d_out, int out_size){
    const float* x     = (const float*)d_in[0];
    const float* W_ih  = (const float*)d_in[1];
    const float* W_hh  = (const float*)d_in[2];
    const float* b     = (const float*)d_in[3];
    const float* W_out = (const float*)d_in[4];

    cudaFuncSetAttribute(lstm_scan, cudaFuncAttributeMaxDynamicSharedMemorySize, SMEM_BYTES);

    xconv_kernel<<<(B_*T_*D_/4)/256, 256>>>(x);
    pack_kernel<<<G_, 256>>>(W_ih, W_hh, b);
    init_kernel<<<256, 256>>>();
    lstm_scan<<<NBLK, THREADS, SMEM_BYTES>>>();
    out_kernel<<<B_, 32>>>(W_out, (float*)d_out);
}